// round 3
// baseline (speedup 1.0000x reference)
#include <cuda_runtime.h>
#include <math.h>

#define N_NODES   24000
#define NT_NODES  8000
#define NUM_T     3
#define NUM_R     34
#define EPR       10000
#define NH        8
#define DKQ       16
#define D         128

// ---------------- scratch (device globals; no allocation allowed) ----------
__device__ float g_k[N_NODES * D];
__device__ float g_q[N_NODES * D];
__device__ float g_v[N_NODES * D];
__device__ float g_qw[N_NODES * NH];
__device__ float g_kw[N_NODES * NH];
__device__ float g_K[(size_t)NUM_R * NT_NODES * D];   // k @ rel_att (pri-scaled), per relation
__device__ float g_V[(size_t)NUM_R * NT_NODES * D];   // v @ rel_msg, per relation
__device__ float g_e[NUM_R * EPR * NH];               // exp(score) per edge/head
__device__ float g_den[NUM_R * NT_NODES * NH];        // softmax denom -> inverted in-place
__device__ unsigned long long g_mask[N_NODES];        // relation bitmask per dst node
__device__ float g_t[N_NODES * D];                    // aggregated messages

// relation -> node-type maps (compile-time formulas from reference)
__device__ __forceinline__ int src_nt(int r) { return r <= 9 ? 0 : (r <= 21 ? 1 : 2); }
__device__ __forceinline__ int dst_nt(int r) {
    if (r <= 2 || (r >= 10 && r <= 13) || (r >= 22 && r <= 24)) return 0;
    if ((r >= 3 && r <= 6) || (r >= 14 && r <= 17) || (r >= 25 && r <= 28)) return 1;
    return 2;
}

// ---------------- zero scratch that is accumulated into ---------------------
__global__ void zero_kernel() {
    int i0 = blockIdx.x * blockDim.x + threadIdx.x;
    int stride = gridDim.x * blockDim.x;
    float4 z = make_float4(0.f, 0.f, 0.f, 0.f);
    float4* den4 = (float4*)g_den;
    for (int i = i0; i < (NUM_R * NT_NODES * NH) / 4; i += stride) den4[i] = z;
    float4* t4 = (float4*)g_t;
    for (int i = i0; i < (N_NODES * D) / 4; i += stride) t4[i] = z;
    for (int i = i0; i < N_NODES; i += stride) g_mask[i] = 0ull;
}

// ---------------- typed K/Q/V projections (3 dense GEMMs per type) ----------
__global__ __launch_bounds__(256) void proj3_kernel(
    const float* __restrict__ x,
    const float* __restrict__ Wk, const float* __restrict__ bk,
    const float* __restrict__ Wq, const float* __restrict__ bq,
    const float* __restrict__ Wv, const float* __restrict__ bv)
{
    __shared__ float xs[64 * D];
    __shared__ float ws[16 * D];
    int node0 = blockIdx.x * 64;
    int t = node0 / NT_NODES;
    int tid = threadIdx.x;
    {
        const float4* xg = (const float4*)(x + (size_t)node0 * D);
        float4* xs4 = (float4*)xs;
        #pragma unroll
        for (int i = 0; i < 8; i++) xs4[tid + i * 256] = xg[tid + i * 256];
    }
    __syncthreads();
    int col = (tid & 31) * 4;
    int row = (tid >> 5) * 8;
    const float* Wp[3] = { Wk + t * D * D, Wq + t * D * D, Wv + t * D * D };
    const float* bp[3] = { bk + t * D,     bq + t * D,     bv + t * D };
    float* op[3] = { g_k, g_q, g_v };
    for (int p = 0; p < 3; p++) {
        float acc[8][4];
        #pragma unroll
        for (int i = 0; i < 8; i++)
            #pragma unroll
            for (int j = 0; j < 4; j++) acc[i][j] = 0.f;
        for (int kc = 0; kc < 8; kc++) {
            __syncthreads();
            const float4* wg = (const float4*)(Wp[p] + kc * 16 * D);
            float4* ws4 = (float4*)ws;
            ws4[tid] = wg[tid];
            ws4[tid + 256] = wg[tid + 256];
            __syncthreads();
            #pragma unroll
            for (int kk = 0; kk < 16; kk++) {
                float4 w = *(const float4*)&ws[kk * D + col];
                #pragma unroll
                for (int i = 0; i < 8; i++) {
                    float xv = xs[(row + i) * D + kc * 16 + kk];
                    acc[i][0] += xv * w.x; acc[i][1] += xv * w.y;
                    acc[i][2] += xv * w.z; acc[i][3] += xv * w.w;
                }
            }
        }
        float4 bb = *(const float4*)&bp[p][col];
        float* o = op[p];
        #pragma unroll
        for (int i = 0; i < 8; i++) {
            float4 rr = make_float4(acc[i][0] + bb.x, acc[i][1] + bb.y,
                                    acc[i][2] + bb.z, acc[i][3] + bb.w);
            *(float4*)&o[(size_t)(node0 + row + i) * D + col] = rr;
        }
    }
}

// ---------------- per-node scalar attention terms q·wq, k·wk ----------------
__global__ void qkw_kernel(const float* __restrict__ attn_w) {
    int idx = blockIdx.x * blockDim.x + threadIdx.x;
    if (idx >= N_NODES * NH) return;
    const float4* q4 = (const float4*)(g_q + (size_t)idx * DKQ);
    const float4* k4 = (const float4*)(g_k + (size_t)idx * DKQ);
    const float4* w4 = (const float4*)attn_w;
    float qs = 0.f, ks = 0.f;
    #pragma unroll
    for (int j = 0; j < 4; j++) {
        float4 q = q4[j], k = k4[j], wq = w4[j], wk = w4[4 + j];
        qs += q.x * wq.x + q.y * wq.y + q.z * wq.z + q.w * wq.w;
        ks += k.x * wk.x + k.y * wk.y + k.z * wk.z + k.w * wk.w;
    }
    g_qw[idx] = qs;
    g_kw[idx] = ks;
}

// ---------------- per-relation node transforms: K_r = k A_r * pri/4, V_r = v M_r
// grid (125, 34, 2): z=0 -> K from rel_att (pri-scaled), z=1 -> V from rel_msg
// block: 256 threads = 32 (node-pairs) x 8 heads; 64 nodes per block.
__global__ __launch_bounds__(256) void rel_transform_kernel(
    const float* __restrict__ rel_att, const float* __restrict__ rel_msg,
    const float* __restrict__ rel_pri)
{
    __shared__ float4 mat4[16 * 4 * NH];   // [dd][f4][h]
    int r = blockIdx.y;
    int z = blockIdx.z;
    int tid = threadIdx.x;
    {
        const float* M = z == 0 ? rel_att : rel_msg;
        float* m = (float*)mat4;
        #pragma unroll
        for (int it = 0; it < 8; it++) {
            int i = tid + it * 256;                  // = h*256 + dd*16 + f
            int hh = i >> 8, dd = (i >> 4) & 15, ff = i & 15;
            float scale = z == 0 ? rel_pri[r * NH + hh] * 0.25f : 1.f;
            m[((dd * 4 + (ff >> 2)) * NH + hh) * 4 + (ff & 3)] = M[r * 2048 + i] * scale;
        }
    }
    __syncthreads();

    int h = tid & 7;
    int nl = tid >> 3;                               // 0..31, two nodes each
    int n0 = blockIdx.x * 64 + nl * 2;               // local node within type
    int snt = src_nt(r);
    const float* in = (z == 0 ? g_k : g_v) + ((size_t)(snt * NT_NODES + n0)) * D + h * DKQ;
    float* outp = (z == 0 ? g_K : g_V) + (((size_t)r * NT_NODES + n0) * NH + h) * DKQ;

    float a[2][16];
    #pragma unroll
    for (int i = 0; i < 2; i++) {
        const float4* p = (const float4*)(in + i * D);
        #pragma unroll
        for (int j = 0; j < 4; j++) {
            float4 v = p[j];
            a[i][j * 4] = v.x; a[i][j * 4 + 1] = v.y; a[i][j * 4 + 2] = v.z; a[i][j * 4 + 3] = v.w;
        }
    }
    float4 acc[2][4];
    #pragma unroll
    for (int i = 0; i < 2; i++)
        #pragma unroll
        for (int f4 = 0; f4 < 4; f4++) acc[i][f4] = make_float4(0.f, 0.f, 0.f, 0.f);
    const float4* mb = mat4 + h;
    #pragma unroll
    for (int dd = 0; dd < 16; dd++) {
        float d0 = a[0][dd], d1 = a[1][dd];
        #pragma unroll
        for (int f4 = 0; f4 < 4; f4++) {
            float4 m = mb[(dd * 4 + f4) * NH];
            acc[0][f4].x += d0 * m.x; acc[0][f4].y += d0 * m.y;
            acc[0][f4].z += d0 * m.z; acc[0][f4].w += d0 * m.w;
            acc[1][f4].x += d1 * m.x; acc[1][f4].y += d1 * m.y;
            acc[1][f4].z += d1 * m.z; acc[1][f4].w += d1 * m.w;
        }
    }
    #pragma unroll
    for (int i = 0; i < 2; i++) {
        float4* o = (float4*)(outp + (size_t)i * NH * DKQ);
        #pragma unroll
        for (int f4 = 0; f4 < 4; f4++) o[f4] = acc[i][f4];
    }
}

// ---------------- edge scores: e = exp(a + beta*na), den accumulation -------
__global__ __launch_bounds__(256) void edge_score_kernel(
    const int* __restrict__ src, const int* __restrict__ dst,
    const float* __restrict__ nta, const float* __restrict__ nta1,
    const float* __restrict__ weight)
{
    int r = blockIdx.y;
    int tid = threadIdx.x;
    int h = tid & 7;
    int el = tid >> 3;
    int snt = src_nt(r), dnt = dst_nt(r);
    float ntaS = nta[snt], ntaD = nta1[dnt];
    float beta = 1.f / (1.f + __expf(-weight[0]));
    int sbase = snt * NT_NODES, dbase = dnt * NT_NODES;

    for (int e = blockIdx.x * 32 + el; e < EPR; e += 32 * gridDim.x) {
        int s = src[r * EPR + e];
        int d = dst[r * EPR + e];
        const float4* Kp = (const float4*)(g_K + (((size_t)r * NT_NODES + (s - sbase)) * NH + h) * DKQ);
        const float4* qp = (const float4*)(g_q + (size_t)d * D + h * DKQ);
        float4 K0 = Kp[0], K1 = Kp[1], K2 = Kp[2], K3 = Kp[3];
        float4 q0 = qp[0], q1 = qp[1], q2 = qp[2], q3 = qp[3];
        float a = K0.x * q0.x + K0.y * q0.y + K0.z * q0.z + K0.w * q0.w
                + K1.x * q1.x + K1.y * q1.y + K1.z * q1.z + K1.w * q1.w
                + K2.x * q2.x + K2.y * q2.y + K2.z * q2.z + K2.w * q2.w
                + K3.x * q3.x + K3.y * q3.y + K3.z * q3.z + K3.w * q3.w;
        float na = ntaD * g_qw[(size_t)d * NH + h] + ntaS * g_kw[(size_t)s * NH + h];
        na = na > 0.f ? na : 0.01f * na;             // leaky_relu(0.01)
        float ev = __expf(a + beta * na);            // max-shift skipped (ratio-invariant)
        g_e[((size_t)r * EPR + e) * NH + h] = ev;
        atomicAdd(&g_den[((size_t)r * NT_NODES + (d - dbase)) * NH + h], ev);
        if (h == 0) atomicOr(&g_mask[d], 1ull << r);
    }
}

// ---------------- invert denominators, folding 1/nrel ------------------------
__global__ void deninv_kernel() {
    int idx = blockIdx.x * blockDim.x + threadIdx.x;
    if (idx >= NUM_R * NT_NODES * NH) return;
    int r = idx / (NT_NODES * NH);
    int rem = idx - r * (NT_NODES * NH);
    int dl = rem / NH;
    int d = dst_nt(r) * NT_NODES + dl;
    int c = __popcll(g_mask[d]);
    c = c > 0 ? c : 1;
    float den = g_den[idx];
    g_den[idx] = den > 0.f ? __fdividef(1.f, den * (float)c) : 0.f;
}

// ---------------- weighted scatter of transformed messages into t ------------
__global__ __launch_bounds__(256) void edge_accum_kernel(
    const int* __restrict__ src, const int* __restrict__ dst)
{
    int r = blockIdx.y;
    int tid = threadIdx.x;
    int h = tid & 7;
    int el = tid >> 3;
    int snt = src_nt(r), dnt = dst_nt(r);
    int sbase = snt * NT_NODES, dbase = dnt * NT_NODES;

    for (int e = blockIdx.x * 32 + el; e < EPR; e += 32 * gridDim.x) {
        int s = src[r * EPR + e];
        int d = dst[r * EPR + e];
        float ev = g_e[((size_t)r * EPR + e) * NH + h];
        float deninv = g_den[((size_t)r * NT_NODES + (d - dbase)) * NH + h];
        float w = ev * deninv;
        const float4* Vp = (const float4*)(g_V + (((size_t)r * NT_NODES + (s - sbase)) * NH + h) * DKQ);
        float* tp = g_t + (size_t)d * D + h * DKQ;
        #pragma unroll
        for (int f4 = 0; f4 < 4; f4++) {
            float4 v = Vp[f4];
            asm volatile("red.global.add.v4.f32 [%0], {%1, %2, %3, %4};"
                         :: "l"(tp + f4 * 4),
                            "f"(v.x * w), "f"(v.y * w), "f"(v.z * w), "f"(v.w * w)
                         : "memory");
        }
    }
}

// ---------------- final typed projection + gated skip ------------------------
__global__ __launch_bounds__(256) void final_kernel(
    const float* __restrict__ x,
    const float* __restrict__ Wa, const float* __restrict__ ba,
    const float* __restrict__ skip, float* __restrict__ out)
{
    __shared__ float xs[64 * D];
    __shared__ float ws[16 * D];
    int node0 = blockIdx.x * 64;
    int t = node0 / NT_NODES;
    int tid = threadIdx.x;
    {
        const float4* tg = (const float4*)(g_t + (size_t)node0 * D);
        float4* xs4 = (float4*)xs;
        #pragma unroll
        for (int i = 0; i < 8; i++) xs4[tid + i * 256] = tg[tid + i * 256];
    }
    __syncthreads();
    int col = (tid & 31) * 4;
    int row = (tid >> 5) * 8;
    const float* Wp = Wa + t * D * D;
    float acc[8][4];
    #pragma unroll
    for (int i = 0; i < 8; i++)
        #pragma unroll
        for (int j = 0; j < 4; j++) acc[i][j] = 0.f;
    for (int kc = 0; kc < 8; kc++) {
        __syncthreads();
        const float4* wg = (const float4*)(Wp + kc * 16 * D);
        float4* ws4 = (float4*)ws;
        ws4[tid] = wg[tid];
        ws4[tid + 256] = wg[tid + 256];
        __syncthreads();
        #pragma unroll
        for (int kk = 0; kk < 16; kk++) {
            float4 w = *(const float4*)&ws[kk * D + col];
            #pragma unroll
            for (int i = 0; i < 8; i++) {
                float xv = xs[(row + i) * D + kc * 16 + kk];
                acc[i][0] += xv * w.x; acc[i][1] += xv * w.y;
                acc[i][2] += xv * w.z; acc[i][3] += xv * w.w;
            }
        }
    }
    float alpha = 1.f / (1.f + __expf(-skip[t]));
    float onema = 1.f - alpha;
    float4 bb = *(const float4*)&ba[t * D + col];
    #pragma unroll
    for (int i = 0; i < 8; i++) {
        size_t off = (size_t)(node0 + row + i) * D + col;
        float4 xv = *(const float4*)&x[off];
        float4 rr;
        rr.x = (acc[i][0] + bb.x) * alpha + xv.x * onema;
        rr.y = (acc[i][1] + bb.y) * alpha + xv.y * onema;
        rr.z = (acc[i][2] + bb.z) * alpha + xv.z * onema;
        rr.w = (acc[i][3] + bb.w) * alpha + xv.w * onema;
        *(float4*)&out[off] = rr;
    }
}

// ---------------- launch ------------------------------------------------------
extern "C" void kernel_launch(void* const* d_in, const int* in_sizes, int n_in,
                              void* d_out, int out_size)
{
    const float* x       = (const float*)d_in[0];
    const int*   src     = (const int*)  d_in[1];
    const int*   dst     = (const int*)  d_in[2];
    const float* Wk      = (const float*)d_in[3];
    const float* bk      = (const float*)d_in[4];
    const float* Wq      = (const float*)d_in[5];
    const float* bq      = (const float*)d_in[6];
    const float* Wv      = (const float*)d_in[7];
    const float* bv      = (const float*)d_in[8];
    const float* Wa      = (const float*)d_in[9];
    const float* ba      = (const float*)d_in[10];
    const float* rel_att = (const float*)d_in[11];
    const float* rel_msg = (const float*)d_in[12];
    const float* rel_pri = (const float*)d_in[13];
    const float* nta     = (const float*)d_in[14];
    const float* nta1    = (const float*)d_in[15];
    const float* skip    = (const float*)d_in[16];
    const float* weight  = (const float*)d_in[17];
    const float* attn_w  = (const float*)d_in[18];
    float* out = (float*)d_out;

    zero_kernel<<<1024, 256>>>();
    proj3_kernel<<<N_NODES / 64, 256>>>(x, Wk, bk, Wq, bq, Wv, bv);
    qkw_kernel<<<(N_NODES * NH + 255) / 256, 256>>>(attn_w);
    rel_transform_kernel<<<dim3(NT_NODES / 64, NUM_R, 2), 256>>>(rel_att, rel_msg, rel_pri);
    edge_score_kernel<<<dim3(64, NUM_R), 256>>>(src, dst, nta, nta1, weight);
    deninv_kernel<<<(NUM_R * NT_NODES * NH + 255) / 256, 256>>>();
    edge_accum_kernel<<<dim3(64, NUM_R), 256>>>(src, dst);
    final_kernel<<<N_NODES / 64, 256>>>(x, Wa, ba, skip, out);
}